// round 1
// baseline (speedup 1.0000x reference)
#include <cuda_runtime.h>
#include <cstddef>

// Scratch (allocation-free rule: __device__ globals)
__device__ float g_Q[512 * 768];        // query  [B, H]
__device__ float g_K[512 * 3 * 768];    // key    [B, M, H]
__device__ float g_V[512 * 3 * 768];    // value  [B, M, H]

// ---------------------------------------------------------------------------
// C[i,j] = sum_k A[i,k] * W[j,k] + bias[j]    (torch Linear: x @ W^T + b)
// A: [M,K] row-major, W: [N,K] row-major, C: [M,N] row-major.
// Tile 128x128x16, 256 threads, 8x8 per-thread register tile.
// Requires M%128==0, N%128==0, K%16==0 (holds: M in {512,1536}, N=K=768).
// ---------------------------------------------------------------------------
__global__ __launch_bounds__(256, 2)
void sgemm_nt_bias(const float* __restrict__ A, const float* __restrict__ W,
                   const float* __restrict__ bias, float* __restrict__ C,
                   int M, int N, int K) {
    constexpr int BM = 128, BN = 128, BK = 16;
    __shared__ float As[BK][BM];
    __shared__ float Bs[BK][BN];

    const int tid = threadIdx.x;
    const int bx = blockIdx.x;   // N tile
    const int by = blockIdx.y;   // M tile

    const float* Ab = A + (size_t)by * BM * K;
    const float* Wb = W + (size_t)bx * BN * K;

    const int lrow = tid >> 1;          // 0..127
    const int lcol = (tid & 1) * 8;     // 0 or 8

    const int tx = tid & 15;            // col group
    const int ty = tid >> 4;            // row group

    float acc[8][8];
#pragma unroll
    for (int i = 0; i < 8; i++)
#pragma unroll
        for (int j = 0; j < 8; j++) acc[i][j] = 0.f;

    for (int k0 = 0; k0 < K; k0 += BK) {
        // global loads (two float4 per operand per thread)
        const float4 a0 = *(const float4*)(Ab + (size_t)lrow * K + k0 + lcol);
        const float4 a1 = *(const float4*)(Ab + (size_t)lrow * K + k0 + lcol + 4);
        const float4 w0 = *(const float4*)(Wb + (size_t)lrow * K + k0 + lcol);
        const float4 w1 = *(const float4*)(Wb + (size_t)lrow * K + k0 + lcol + 4);

        __syncthreads();   // previous iteration's reads complete before overwrite
        As[lcol + 0][lrow] = a0.x; As[lcol + 1][lrow] = a0.y;
        As[lcol + 2][lrow] = a0.z; As[lcol + 3][lrow] = a0.w;
        As[lcol + 4][lrow] = a1.x; As[lcol + 5][lrow] = a1.y;
        As[lcol + 6][lrow] = a1.z; As[lcol + 7][lrow] = a1.w;
        Bs[lcol + 0][lrow] = w0.x; Bs[lcol + 1][lrow] = w0.y;
        Bs[lcol + 2][lrow] = w0.z; Bs[lcol + 3][lrow] = w0.w;
        Bs[lcol + 4][lrow] = w1.x; Bs[lcol + 5][lrow] = w1.y;
        Bs[lcol + 6][lrow] = w1.z; Bs[lcol + 7][lrow] = w1.w;
        __syncthreads();

#pragma unroll
        for (int k = 0; k < BK; k++) {
            const float4 x0 = *(const float4*)&As[k][ty * 8];
            const float4 x1 = *(const float4*)&As[k][ty * 8 + 4];
            const float4 y0 = *(const float4*)&Bs[k][tx * 8];
            const float4 y1 = *(const float4*)&Bs[k][tx * 8 + 4];
            const float ar[8] = {x0.x, x0.y, x0.z, x0.w, x1.x, x1.y, x1.z, x1.w};
            const float br[8] = {y0.x, y0.y, y0.z, y0.w, y1.x, y1.y, y1.z, y1.w};
#pragma unroll
            for (int i = 0; i < 8; i++)
#pragma unroll
                for (int j = 0; j < 8; j++) acc[i][j] += ar[i] * br[j];
        }
    }

    const int crow0 = by * BM + ty * 8;
    const int ccol0 = bx * BN + tx * 8;
    float bvreg[8];
#pragma unroll
    for (int j = 0; j < 8; j++) bvreg[j] = bias[ccol0 + j];
#pragma unroll
    for (int i = 0; i < 8; i++) {
        float* Crow = C + (size_t)(crow0 + i) * N + ccol0;
        float4 o0, o1;
        o0.x = acc[i][0] + bvreg[0]; o0.y = acc[i][1] + bvreg[1];
        o0.z = acc[i][2] + bvreg[2]; o0.w = acc[i][3] + bvreg[3];
        o1.x = acc[i][4] + bvreg[4]; o1.y = acc[i][5] + bvreg[5];
        o1.z = acc[i][6] + bvreg[6]; o1.w = acc[i][7] + bvreg[7];
        *(float4*)(Crow)     = o0;
        *(float4*)(Crow + 4) = o1;
    }
}

// ---------------------------------------------------------------------------
// Per-batch epilogue. One block per batch element b (512 blocks, 256 thr).
//   kv[m]  = sum_h p[m,h]*q[h]
//   kr[m]  = sum_{m',h} q[h]*k[m',h]*hmat[(m'*768+h)*3 + m]
//   ker[m] = kv[m]+kr[m]
//   VV[m,m'] = <v[m], v[m']>   (3x3 Gram; replaces the [B,H,H] tensor)
//   c[m']  = sum_m ker[m]*VV[m,m']
//   out[h] = sum_m ker[m]*v[m,h] + sum_{m'} c[m']*g[m',h]
// ---------------------------------------------------------------------------
__global__ __launch_bounds__(256)
void epilogue_kernel(const float* __restrict__ Q,
                     const float* __restrict__ Km,
                     const float* __restrict__ Vm,
                     const float* __restrict__ p,
                     const float* __restrict__ hmat,
                     const float* __restrict__ g,
                     float* __restrict__ out) {
    const int b = blockIdx.x;
    const int tid = threadIdx.x;

    __shared__ float sq[768];
    __shared__ float sk[3 * 768];
    __shared__ float sv[3 * 768];
    __shared__ float racc[12];

    for (int i = tid; i < 768; i += 256) sq[i] = Q[(size_t)b * 768 + i];
    for (int i = tid; i < 2304; i += 256) {
        sk[i] = Km[(size_t)b * 2304 + i];
        sv[i] = Vm[(size_t)b * 2304 + i];
    }
    if (tid < 12) racc[tid] = 0.f;
    __syncthreads();

    // 12 accumulators: kv0..2, kr0..2, vv00,01,02,11,12,22
    float a[12];
#pragma unroll
    for (int i = 0; i < 12; i++) a[i] = 0.f;

    for (int hh = tid; hh < 768; hh += 256) {
        const float q = sq[hh];
        const float v0 = sv[hh], v1 = sv[768 + hh], v2 = sv[1536 + hh];
        a[0] += p[hh] * q;
        a[1] += p[768 + hh] * q;
        a[2] += p[1536 + hh] * q;
#pragma unroll
        for (int mp = 0; mp < 3; mp++) {
            const float t = q * sk[mp * 768 + hh];
            const float* hr = hmat + ((size_t)(mp * 768 + hh)) * 3;
            a[3] += t * hr[0];
            a[4] += t * hr[1];
            a[5] += t * hr[2];
        }
        a[6]  += v0 * v0; a[7]  += v0 * v1; a[8]  += v0 * v2;
        a[9]  += v1 * v1; a[10] += v1 * v2; a[11] += v2 * v2;
    }

#pragma unroll
    for (int i = 0; i < 12; i++) {
        float v = a[i];
#pragma unroll
        for (int off = 16; off; off >>= 1)
            v += __shfl_down_sync(0xffffffffu, v, off);
        if ((tid & 31) == 0) atomicAdd(&racc[i], v);
    }
    __syncthreads();

    const float ker0 = racc[0] + racc[3];
    const float ker1 = racc[1] + racc[4];
    const float ker2 = racc[2] + racc[5];
    const float vv00 = racc[6], vv01 = racc[7], vv02 = racc[8];
    const float vv11 = racc[9], vv12 = racc[10], vv22 = racc[11];
    const float c0 = ker0 * vv00 + ker1 * vv01 + ker2 * vv02;
    const float c1 = ker0 * vv01 + ker1 * vv11 + ker2 * vv12;
    const float c2 = ker0 * vv02 + ker1 * vv12 + ker2 * vv22;

    for (int hh = tid; hh < 768; hh += 256) {
        out[(size_t)b * 768 + hh] =
            ker0 * sv[hh] + ker1 * sv[768 + hh] + ker2 * sv[1536 + hh] +
            c0 * g[hh] + c1 * g[768 + hh] + c2 * g[1536 + hh];
    }
}

extern "C" void kernel_launch(void* const* d_in, const int* in_sizes, int n_in,
                              void* d_out, int out_size) {
    const float* target = (const float*)d_in[0];
    const float* cont   = (const float*)d_in[1];
    const float* Wq     = (const float*)d_in[2];
    const float* bq     = (const float*)d_in[3];
    const float* Wk     = (const float*)d_in[4];
    const float* bk     = (const float*)d_in[5];
    const float* Wv     = (const float*)d_in[6];
    const float* bv     = (const float*)d_in[7];
    const float* p      = (const float*)d_in[8];
    const float* hmat   = (const float*)d_in[9];
    const float* g      = (const float*)d_in[10];
    float* out = (float*)d_out;

    float *dQ = nullptr, *dK = nullptr, *dV = nullptr;
    cudaGetSymbolAddress((void**)&dQ, g_Q);
    cudaGetSymbolAddress((void**)&dK, g_K);
    cudaGetSymbolAddress((void**)&dV, g_V);

    dim3 blk(256);
    sgemm_nt_bias<<<dim3(6, 4),  blk>>>(target, Wq, bq, dQ, 512,  768, 768);
    sgemm_nt_bias<<<dim3(6, 12), blk>>>(cont,   Wk, bk, dK, 1536, 768, 768);
    sgemm_nt_bias<<<dim3(6, 12), blk>>>(cont,   Wv, bv, dV, 1536, 768, 768);
    epilogue_kernel<<<512, 256>>>(dQ, dK, dV, p, hmat, g, out);
}

// round 2
// speedup vs baseline: 2.0698x; 2.0698x over previous
#include <cuda_runtime.h>
#include <cstdint>
#include <cstddef>

// Scratch (allocation-free rule: __device__ globals)
__device__ float g_Q[512 * 768];        // query  [B, H]
__device__ float g_K[512 * 3 * 768];    // key    [B, M, H]
__device__ float g_V[512 * 3 * 768];    // value  [B, M, H]

#define HDIM 768
#define BMT  128   // CTA tile M
#define BNT  64    // CTA tile N
#define BKT  8     // CTA tile K (one k8 mma step per stage)
#define SA   136   // A smem k-row stride in floats (128 + 8 pad, 2-way max conflict)
#define SB   12    // B smem n-row stride in floats (8 + 4 pad)

__device__ __forceinline__ uint32_t f32_to_tf32(float x) {
    uint32_t r;
    asm("cvt.rna.tf32.f32 %0, %1;" : "=r"(r) : "f"(x));
    return r;
}

__device__ __forceinline__ void mma_tf32(float* c, uint32_t a0, uint32_t a1,
                                         uint32_t a2, uint32_t a3,
                                         uint32_t b0, uint32_t b1) {
    asm volatile(
        "mma.sync.aligned.m16n8k8.row.col.f32.tf32.tf32.f32 "
        "{%0,%1,%2,%3}, {%4,%5,%6,%7}, {%8,%9}, {%0,%1,%2,%3};"
        : "+f"(c[0]), "+f"(c[1]), "+f"(c[2]), "+f"(c[3])
        : "r"(a0), "r"(a1), "r"(a2), "r"(a3), "r"(b0), "r"(b1));
}

// ---------------------------------------------------------------------------
// Fused Q/K/V linear layers, one launch. C = A @ W^T + bias.
// Grid: 336 CTAs total: [0,48)=Q (M=512), [48,192)=K, [192,336)=V (M=1536).
// CTA tile 128x64, warp tile 32x32 (8 warps as 4x2), 3xTF32 mma.sync.
// ---------------------------------------------------------------------------
__global__ __launch_bounds__(256, 2)
void qkv_gemm_tf32(const float* __restrict__ target,
                   const float* __restrict__ cont,
                   const float* __restrict__ Wq, const float* __restrict__ bq,
                   const float* __restrict__ Wk, const float* __restrict__ bk,
                   const float* __restrict__ Wv, const float* __restrict__ bv,
                   float* __restrict__ Qo, float* __restrict__ Ko,
                   float* __restrict__ Vo)
{
    int blk = blockIdx.x;
    const float *A, *W, *bias;
    float* C;
    int by, bx;
    if (blk < 48)       { int t = blk;       by = t / 12; bx = t % 12; A = target; W = Wq; bias = bq; C = Qo; }
    else if (blk < 192) { int t = blk - 48;  by = t / 12; bx = t % 12; A = cont;   W = Wk; bias = bk; C = Ko; }
    else                { int t = blk - 192; by = t / 12; bx = t % 12; A = cont;   W = Wv; bias = bv; C = Vo; }

    __shared__ float Ah[2][BKT * SA];
    __shared__ float Al[2][BKT * SA];
    __shared__ float Bh[2][BNT * SB];
    __shared__ float Bl[2][BNT * SB];

    const int tid  = threadIdx.x;
    const int lane = tid & 31;
    const int wid  = tid >> 5;
    const int g    = lane >> 2;   // group 0..7
    const int tig  = lane & 3;    // thread-in-group 0..3
    const int warp_m = (wid >> 1) * 32;   // 4 warps along M
    const int warp_n = (wid & 1) * 32;    // 2 warps along N

    // Global load mapping: A tile 128x8 -> 256 float4 (1/thread);
    //                      B tile  64x8 -> 128 float4 (threads 0..127).
    const int arow = tid >> 1;          // 0..127
    const int akv  = (tid & 1) * 4;     // 0 or 4 (k sub-vector)
    const float* Aptr = A + (size_t)(by * BMT + arow) * HDIM + akv;
    const int brow = (tid & 127) >> 1;  // 0..63
    const float* Bptr = W + (size_t)(bx * BNT + brow) * HDIM + akv;
    const bool bactive = tid < 128;

    // Permuted smem index for A rows: within each 16-row block, order rows so
    // (m, m+8) become an adjacent float2 pair -> fragment loads are LDS.64.
    const int permA = ((arow >> 4) << 4) + ((arow & 7) << 1) + ((arow >> 3) & 1);
    // B perm: pair (k, k+4) adjacent: perm = (k&3)*2 + (k>>2). With k=akv+j:
    const int bsel = akv >> 2;          // 0 or 1

    float acc[2][4][4];
#pragma unroll
    for (int mt = 0; mt < 2; mt++)
#pragma unroll
        for (int nt = 0; nt < 4; nt++)
#pragma unroll
            for (int i = 0; i < 4; i++) acc[mt][nt][i] = 0.f;

    // ---- prologue: stage 0 ----
    float4 a4 = *(const float4*)Aptr;
    float4 b4 = bactive ? *(const float4*)Bptr : make_float4(0.f, 0.f, 0.f, 0.f);
    {
        const float av[4] = {a4.x, a4.y, a4.z, a4.w};
        const float bv4[4] = {b4.x, b4.y, b4.z, b4.w};
#pragma unroll
        for (int j = 0; j < 4; j++) {
            uint32_t hi = f32_to_tf32(av[j]);
            uint32_t lo = f32_to_tf32(av[j] - __uint_as_float(hi));
            Ah[0][(akv + j) * SA + permA] = __uint_as_float(hi);
            Al[0][(akv + j) * SA + permA] = __uint_as_float(lo);
        }
        if (bactive) {
#pragma unroll
            for (int j = 0; j < 4; j++) {
                uint32_t hi = f32_to_tf32(bv4[j]);
                uint32_t lo = f32_to_tf32(bv4[j] - __uint_as_float(hi));
                Bh[0][brow * SB + j * 2 + bsel] = __uint_as_float(hi);
                Bl[0][brow * SB + j * 2 + bsel] = __uint_as_float(lo);
            }
        }
    }
    __syncthreads();

    int buf = 0;
    for (int k0 = BKT; k0 <= HDIM; k0 += BKT) {
        const bool more = (k0 < HDIM);
        float4 na, nb;
        if (more) {
            na = *(const float4*)(Aptr + k0);
            if (bactive) nb = *(const float4*)(Bptr + k0);
        }

        // ---- compute current stage ----
        {
            float2 bhf[4], blf[4];
#pragma unroll
            for (int nt = 0; nt < 4; nt++) {
                const int n = warp_n + nt * 8 + g;
                bhf[nt] = *(const float2*)&Bh[buf][n * SB + tig * 2];
                blf[nt] = *(const float2*)&Bl[buf][n * SB + tig * 2];
            }
#pragma unroll
            for (int mt = 0; mt < 2; mt++) {
                const int mbase = warp_m + mt * 16;  // multiple of 16: perm-invariant base
                const float2 a01h = *(const float2*)&Ah[buf][tig * SA + mbase + g * 2];
                const float2 a23h = *(const float2*)&Ah[buf][(tig + 4) * SA + mbase + g * 2];
                const float2 a01l = *(const float2*)&Al[buf][tig * SA + mbase + g * 2];
                const float2 a23l = *(const float2*)&Al[buf][(tig + 4) * SA + mbase + g * 2];
                const uint32_t ah0 = __float_as_uint(a01h.x), ah1 = __float_as_uint(a01h.y);
                const uint32_t ah2 = __float_as_uint(a23h.x), ah3 = __float_as_uint(a23h.y);
                const uint32_t al0 = __float_as_uint(a01l.x), al1 = __float_as_uint(a01l.y);
                const uint32_t al2 = __float_as_uint(a23l.x), al3 = __float_as_uint(a23l.y);
#pragma unroll
                for (int nt = 0; nt < 4; nt++) {
                    const uint32_t bh0 = __float_as_uint(bhf[nt].x), bh1 = __float_as_uint(bhf[nt].y);
                    const uint32_t bl0 = __float_as_uint(blf[nt].x), bl1 = __float_as_uint(blf[nt].y);
                    mma_tf32(acc[mt][nt], ah0, ah1, ah2, ah3, bh0, bh1);  // hh
                    mma_tf32(acc[mt][nt], ah0, ah1, ah2, ah3, bl0, bl1);  // hl
                    mma_tf32(acc[mt][nt], al0, al1, al2, al3, bh0, bh1);  // lh
                }
            }
        }

        // ---- store next stage ----
        if (more) {
            const int nx = buf ^ 1;
            const float av[4] = {na.x, na.y, na.z, na.w};
#pragma unroll
            for (int j = 0; j < 4; j++) {
                uint32_t hi = f32_to_tf32(av[j]);
                uint32_t lo = f32_to_tf32(av[j] - __uint_as_float(hi));
                Ah[nx][(akv + j) * SA + permA] = __uint_as_float(hi);
                Al[nx][(akv + j) * SA + permA] = __uint_as_float(lo);
            }
            if (bactive) {
                const float bv4[4] = {nb.x, nb.y, nb.z, nb.w};
#pragma unroll
                for (int j = 0; j < 4; j++) {
                    uint32_t hi = f32_to_tf32(bv4[j]);
                    uint32_t lo = f32_to_tf32(bv4[j] - __uint_as_float(hi));
                    Bh[nx][brow * SB + j * 2 + bsel] = __uint_as_float(hi);
                    Bl[nx][brow * SB + j * 2 + bsel] = __uint_as_float(lo);
                }
            }
        }
        __syncthreads();
        buf ^= 1;
    }

    // ---- epilogue: bias add + store ----
#pragma unroll
    for (int mt = 0; mt < 2; mt++) {
        const int row0 = by * BMT + warp_m + mt * 16 + g;
#pragma unroll
        for (int nt = 0; nt < 4; nt++) {
            const int col = bx * BNT + warp_n + nt * 8 + tig * 2;
            const float2 bb = *(const float2*)&bias[col];
            float2 o0, o1;
            o0.x = acc[mt][nt][0] + bb.x;
            o0.y = acc[mt][nt][1] + bb.y;
            o1.x = acc[mt][nt][2] + bb.x;
            o1.y = acc[mt][nt][3] + bb.y;
            *(float2*)(C + (size_t)row0 * HDIM + col)       = o0;
            *(float2*)(C + (size_t)(row0 + 8) * HDIM + col) = o1;
        }
    }
}

// ---------------------------------------------------------------------------
// Per-batch epilogue (unchanged from R0; 15.9us). One block per batch b.
// ---------------------------------------------------------------------------
__global__ __launch_bounds__(256)
void epilogue_kernel(const float* __restrict__ Q,
                     const float* __restrict__ Km,
                     const float* __restrict__ Vm,
                     const float* __restrict__ p,
                     const float* __restrict__ hmat,
                     const float* __restrict__ g,
                     float* __restrict__ out) {
    const int b = blockIdx.x;
    const int tid = threadIdx.x;

    __shared__ float sq[768];
    __shared__ float sk[3 * 768];
    __shared__ float sv[3 * 768];
    __shared__ float racc[12];

    for (int i = tid; i < 768; i += 256) sq[i] = Q[(size_t)b * 768 + i];
    for (int i = tid; i < 2304; i += 256) {
        sk[i] = Km[(size_t)b * 2304 + i];
        sv[i] = Vm[(size_t)b * 2304 + i];
    }
    if (tid < 12) racc[tid] = 0.f;
    __syncthreads();

    float a[12];
#pragma unroll
    for (int i = 0; i < 12; i++) a[i] = 0.f;

    for (int hh = tid; hh < 768; hh += 256) {
        const float q = sq[hh];
        const float v0 = sv[hh], v1 = sv[768 + hh], v2 = sv[1536 + hh];
        a[0] += p[hh] * q;
        a[1] += p[768 + hh] * q;
        a[2] += p[1536 + hh] * q;
#pragma unroll
        for (int mp = 0; mp < 3; mp++) {
            const float t = q * sk[mp * 768 + hh];
            const float* hr = hmat + ((size_t)(mp * 768 + hh)) * 3;
            a[3] += t * hr[0];
            a[4] += t * hr[1];
            a[5] += t * hr[2];
        }
        a[6]  += v0 * v0; a[7]  += v0 * v1; a[8]  += v0 * v2;
        a[9]  += v1 * v1; a[10] += v1 * v2; a[11] += v2 * v2;
    }

#pragma unroll
    for (int i = 0; i < 12; i++) {
        float v = a[i];
#pragma unroll
        for (int off = 16; off; off >>= 1)
            v += __shfl_down_sync(0xffffffffu, v, off);
        if ((tid & 31) == 0) atomicAdd(&racc[i], v);
    }
    __syncthreads();

    const float ker0 = racc[0] + racc[3];
    const float ker1 = racc[1] + racc[4];
    const float ker2 = racc[2] + racc[5];
    const float vv00 = racc[6], vv01 = racc[7], vv02 = racc[8];
    const float vv11 = racc[9], vv12 = racc[10], vv22 = racc[11];
    const float c0 = ker0 * vv00 + ker1 * vv01 + ker2 * vv02;
    const float c1 = ker0 * vv01 + ker1 * vv11 + ker2 * vv12;
    const float c2 = ker0 * vv02 + ker1 * vv12 + ker2 * vv22;

    for (int hh = tid; hh < 768; hh += 256) {
        out[(size_t)b * 768 + hh] =
            ker0 * sv[hh] + ker1 * sv[768 + hh] + ker2 * sv[1536 + hh] +
            c0 * g[hh] + c1 * g[768 + hh] + c2 * g[1536 + hh];
    }
}

extern "C" void kernel_launch(void* const* d_in, const int* in_sizes, int n_in,
                              void* d_out, int out_size) {
    const float* target = (const float*)d_in[0];
    const float* cont   = (const float*)d_in[1];
    const float* Wq     = (const float*)d_in[2];
    const float* bq     = (const float*)d_in[3];
    const float* Wk     = (const float*)d_in[4];
    const float* bk     = (const float*)d_in[5];
    const float* Wv     = (const float*)d_in[6];
    const float* bv     = (const float*)d_in[7];
    const float* p      = (const float*)d_in[8];
    const float* hmat   = (const float*)d_in[9];
    const float* g      = (const float*)d_in[10];
    float* out = (float*)d_out;

    float *dQ = nullptr, *dK = nullptr, *dV = nullptr;
    cudaGetSymbolAddress((void**)&dQ, g_Q);
    cudaGetSymbolAddress((void**)&dK, g_K);
    cudaGetSymbolAddress((void**)&dV, g_V);

    qkv_gemm_tf32<<<336, 256>>>(target, cont, Wq, bq, Wk, bk, Wv, bv, dQ, dK, dV);
    epilogue_kernel<<<512, 256>>>(dQ, dK, dV, p, hmat, g, out);
}

// round 4
// speedup vs baseline: 3.4334x; 1.6588x over previous
#include <cuda_runtime.h>
#include <cuda_bf16.h>
#include <cstdint>
#include <cstddef>

// ---------------- scratch (allocation-free rule: __device__ globals) --------
__device__ float g_Q[512 * 768];
__device__ float g_K[1536 * 768];
__device__ float g_V[1536 * 768];

// bf16 hi/lo planes. A = [target(512) ; cont(1536)] rows of 768.
__device__ __align__(16) __nv_bfloat16 g_Ah[2048 * 768];
__device__ __align__(16) __nv_bfloat16 g_Al[2048 * 768];
__device__ __align__(16) __nv_bfloat16 g_Wh[3 * 768 * 768];   // Wq|Wk|Wv
__device__ __align__(16) __nv_bfloat16 g_Wl[3 * 768 * 768];

// ---------------- helpers ---------------------------------------------------
__device__ __forceinline__ uint32_t smem_u32(const void* p) {
    uint32_t a;
    asm("{ .reg .u64 t; cvta.to.shared.u64 t, %1; cvt.u32.u64 %0, t; }" : "=r"(a) : "l"(p));
    return a;
}
__device__ __forceinline__ void cp16(uint32_t dst, const void* src) {
    asm volatile("cp.async.cg.shared.global [%0], [%1], 16;" :: "r"(dst), "l"(src) : "memory");
}
__device__ __forceinline__ void cp_commit() {
    asm volatile("cp.async.commit_group;" ::: "memory");
}
__device__ __forceinline__ void ldmx4(uint32_t* r, uint32_t addr) {
    asm volatile("ldmatrix.sync.aligned.m8n8.x4.shared.b16 {%0,%1,%2,%3}, [%4];"
                 : "=r"(r[0]), "=r"(r[1]), "=r"(r[2]), "=r"(r[3]) : "r"(addr));
}
__device__ __forceinline__ void mma_bf16(float* c, const uint32_t* a,
                                         uint32_t b0, uint32_t b1) {
    asm volatile(
        "mma.sync.aligned.m16n8k16.row.col.f32.bf16.bf16.f32 "
        "{%0,%1,%2,%3}, {%4,%5,%6,%7}, {%8,%9}, {%0,%1,%2,%3};"
        : "+f"(c[0]), "+f"(c[1]), "+f"(c[2]), "+f"(c[3])
        : "r"(a[0]), "r"(a[1]), "r"(a[2]), "r"(a[3]), "r"(b0), "r"(b1));
}

// ---------------- pre-pass: fp32 -> bf16 hi/lo split ------------------------
// float4 index space: [0,98304) target, [98304,393216) cont,
// [393216,835584) W planes (147456 float4 each: Wq, Wk, Wv).
__global__ __launch_bounds__(256)
void split_bf16_kernel(const float* __restrict__ t, const float* __restrict__ c,
                       const float* __restrict__ wq, const float* __restrict__ wk,
                       const float* __restrict__ wv) {
    int idx = blockIdx.x * 256 + threadIdx.x;
    if (idx >= 835584) return;
    float4 x;
    __nv_bfloat16 *dh, *dl;
    size_t slot;
    if (idx < 393216) {
        x = (idx < 98304) ? ((const float4*)t)[idx] : ((const float4*)c)[idx - 98304];
        dh = g_Ah; dl = g_Al; slot = idx;
    } else {
        int w = idx - 393216;
        int plane = w / 147456, wi = w % 147456;
        const float4* s = (const float4*)(plane == 0 ? wq : (plane == 1 ? wk : wv));
        x = s[wi];
        dh = g_Wh; dl = g_Wl; slot = w;
    }
    const float xs[4] = {x.x, x.y, x.z, x.w};
    unsigned short hs[4], ls[4];
#pragma unroll
    for (int j = 0; j < 4; j++) {
        __nv_bfloat16 h = __float2bfloat16_rn(xs[j]);
        float r = xs[j] - __bfloat162float(h);
        __nv_bfloat16 l = __float2bfloat16_rn(r);
        hs[j] = __bfloat16_as_ushort(h);
        ls[j] = __bfloat16_as_ushort(l);
    }
    uint2 ph, pl;
    ph.x = (uint32_t)hs[0] | ((uint32_t)hs[1] << 16);
    ph.y = (uint32_t)hs[2] | ((uint32_t)hs[3] << 16);
    pl.x = (uint32_t)ls[0] | ((uint32_t)ls[1] << 16);
    pl.y = (uint32_t)ls[2] | ((uint32_t)ls[3] << 16);
    ((uint2*)dh)[slot] = ph;
    ((uint2*)dl)[slot] = pl;
}

// ---------------- fused QKV GEMM: bf16x3 mma.sync m16n8k16 ------------------
// C = A @ W^T + bias. 336 CTAs of BM=128 x BN=64 tiles:
//   [0,48)=Q (512x768), [48,192)=K, [192,336)=V (1536x768 each).
// K chunked by 16, cp.async double buffer, ldmatrix from 48B-stride rows.
// 8 warps as 2x4: warp tile 64x16. Per warp per chunk: 24 mma.
#define SROW 48                        // smem row stride bytes (32B data + 16 pad)
#define APL  (128 * SROW)              // 6144
#define BPL  (64 * SROW)               // 3072
#define STAGE (2 * APL + 2 * BPL)      // 18432
#define NCH  48

__global__ __launch_bounds__(256, 2)
void qkv_gemm_bf16(const float* __restrict__ bq, const float* __restrict__ bk,
                   const float* __restrict__ bv) {
    __shared__ __align__(16) char smem[2 * STAGE];
    const uint32_t sb = smem_u32(smem);

    const int tid = threadIdx.x, lane = tid & 31, wid = tid >> 5;
    const int blk = blockIdx.x;

    int by, bx, rowA0, plane;
    const float* bias;
    float* C;
    if (blk < 48)       { int t = blk;       by = t / 12; bx = t % 12; rowA0 = by * 128;       plane = 0; bias = bq; C = g_Q; }
    else if (blk < 192) { int t = blk - 48;  by = t / 12; bx = t % 12; rowA0 = 512 + by * 128; plane = 1; bias = bk; C = g_K; }
    else                { int t = blk - 192; by = t / 12; bx = t % 12; rowA0 = 512 + by * 128; plane = 2; bias = bv; C = g_V; }

    const char* srcAh = (const char*)g_Ah + (size_t)rowA0 * 1536;
    const char* srcAl = (const char*)g_Al + (size_t)rowA0 * 1536;
    const char* srcBh = (const char*)g_Wh + (size_t)plane * 1179648 + (size_t)(bx * 64) * 1536;
    const char* srcBl = (const char*)g_Wl + (size_t)plane * 1179648 + (size_t)(bx * 64) * 1536;

    // --- load decode: 768 cp16 per stage, 3 per thread -----------------------
    // id < 512: A plane=id>>8, rem=id&255, row=rem>>1, sub=rem&1
    // id >=512: B plane=(id-512)>>7, rem&127, row=rem>>1, sub=rem&1
    int lrow[3], lsub[3];
    uint32_t ldst[3];
    const char* lsrc[3];
#pragma unroll
    for (int i = 0; i < 3; i++) {
        const int id = i * 256 + tid;
        if (id < 512) {
            const int pl = id >> 8, rem = id & 255, row = rem >> 1, sub = rem & 1;
            lrow[i] = row; lsub[i] = sub;
            ldst[i] = (pl ? APL : 0) + row * SROW + sub * 16;
            lsrc[i] = (pl ? srcAl : srcAh) + (size_t)row * 1536 + sub * 16;
        } else {
            const int id2 = id - 512;
            const int pl = id2 >> 7, rem = id2 & 127, row = rem >> 1, sub = rem & 1;
            lrow[i] = row; lsub[i] = sub;
            ldst[i] = 2 * APL + (pl ? BPL : 0) + row * SROW + sub * 16;
            lsrc[i] = (pl ? srcBl : srcBh) + (size_t)row * 1536 + sub * 16;
        }
    }

    const int warp_m = (wid >> 2) * 64;   // 0 or 64
    const int warp_n = (wid & 3) * 16;    // 0,16,32,48

    // ldmatrix addressing
    const int a_row = lane & 15;
    const int a_koff = ((lane >> 4) & 1) * 16;
    const int b_row = ((lane >> 4) & 1) * 8 + (lane & 7);
    const int b_koff = ((lane >> 3) & 1) * 16;

    float acc[4][2][4];
#pragma unroll
    for (int mf = 0; mf < 4; mf++)
#pragma unroll
        for (int nf = 0; nf < 2; nf++)
#pragma unroll
            for (int i = 0; i < 4; i++) acc[mf][nf][i] = 0.f;

    // prologue: stage 0
#pragma unroll
    for (int i = 0; i < 3; i++) cp16(sb + ldst[i], lsrc[i]);
    cp_commit();

    for (int c = 0; c < NCH; c++) {
        const int buf = c & 1;
        if (c + 1 < NCH) {
            const uint32_t nb = sb + (buf ^ 1) * STAGE;
            const size_t off = (size_t)(c + 1) * 32;
#pragma unroll
            for (int i = 0; i < 3; i++) cp16(nb + ldst[i], lsrc[i] + off);
            cp_commit();
            asm volatile("cp.async.wait_group 1;" ::: "memory");
        } else {
            asm volatile("cp.async.wait_group 0;" ::: "memory");
        }
        __syncthreads();

        const uint32_t st = sb + buf * STAGE;
        uint32_t ah[4][4], al[4][4], bh[4], bl[4];
#pragma unroll
        for (int mf = 0; mf < 4; mf++) {
            const uint32_t ra = st + (warp_m + mf * 16 + a_row) * SROW + a_koff;
            ldmx4(ah[mf], ra);
            ldmx4(al[mf], ra + APL);
        }
        {
            const uint32_t rb = st + 2 * APL + (warp_n + b_row) * SROW + b_koff;
            ldmx4(bh, rb);
            ldmx4(bl, rb + BPL);
        }
#pragma unroll
        for (int mf = 0; mf < 4; mf++) {
#pragma unroll
            for (int nf = 0; nf < 2; nf++) {
                mma_bf16(acc[mf][nf], ah[mf], bh[nf * 2], bh[nf * 2 + 1]);  // hh
                mma_bf16(acc[mf][nf], ah[mf], bl[nf * 2], bl[nf * 2 + 1]);  // hl
                mma_bf16(acc[mf][nf], al[mf], bh[nf * 2], bh[nf * 2 + 1]);  // lh
            }
        }
        __syncthreads();
    }

    // epilogue: bias + store fp32
    const int g4 = lane >> 2, t4 = lane & 3;
    const int outM0 = (blk < 48 ? by * 128 : (by * 128));  // row within C
#pragma unroll
    for (int mf = 0; mf < 4; mf++) {
        const int row = outM0 + warp_m + mf * 16 + g4;
#pragma unroll
        for (int nf = 0; nf < 2; nf++) {
            const int col = bx * 64 + warp_n + nf * 8 + t4 * 2;
            const float2 bb = *(const float2*)&bias[col];
            float2 o0, o1;
            o0.x = acc[mf][nf][0] + bb.x; o0.y = acc[mf][nf][1] + bb.y;
            o1.x = acc[mf][nf][2] + bb.x; o1.y = acc[mf][nf][3] + bb.y;
            *(float2*)&C[(size_t)row * 768 + col]       = o0;
            *(float2*)&C[(size_t)(row + 8) * 768 + col] = o1;
        }
    }
}

// ---------------- per-batch epilogue (vectorized) ---------------------------
__global__ __launch_bounds__(256)
void batch_epilogue(const float* __restrict__ p, const float* __restrict__ hmat,
                    const float* __restrict__ g, float* __restrict__ out) {
    const int b = blockIdx.x, tid = threadIdx.x;
    __shared__ float racc[12];
    if (tid < 12) racc[tid] = 0.f;
    __syncthreads();

    const bool act = tid < 192;
    const int hh = tid * 4;
    float a[12];
#pragma unroll
    for (int i = 0; i < 12; i++) a[i] = 0.f;

    float4 v4[3];
    if (act) {
        const float4 q4 = *(const float4*)&g_Q[(size_t)b * 768 + hh];
#pragma unroll
        for (int mp = 0; mp < 3; mp++) {
            const float4 k4 = *(const float4*)&g_K[((size_t)b * 3 + mp) * 768 + hh];
            v4[mp]          = *(const float4*)&g_V[((size_t)b * 3 + mp) * 768 + hh];
            const float4 pm = *(const float4*)&p[mp * 768 + hh];
            a[mp] += pm.x * q4.x + pm.y * q4.y + pm.z * q4.z + pm.w * q4.w;

            const float4* hrp = (const float4*)&hmat[((size_t)(mp * 768 + hh)) * 3];
            const float4 f0 = hrp[0], f1 = hrp[1], f2 = hrp[2];
            const float hr[12] = {f0.x, f0.y, f0.z, f0.w, f1.x, f1.y,
                                  f1.z, f1.w, f2.x, f2.y, f2.z, f2.w};
            const float t[4] = {q4.x * k4.x, q4.y * k4.y, q4.z * k4.z, q4.w * k4.w};
#pragma unroll
            for (int e = 0; e < 4; e++) {
                a[3] += t[e] * hr[e * 3 + 0];
                a[4] += t[e] * hr[e * 3 + 1];
                a[5] += t[e] * hr[e * 3 + 2];
            }
        }
        const float4 v0 = v4[0], v1 = v4[1], v2 = v4[2];
        a[6]  += v0.x*v0.x + v0.y*v0.y + v0.z*v0.z + v0.w*v0.w;
        a[7]  += v0.x*v1.x + v0.y*v1.y + v0.z*v1.z + v0.w*v1.w;
        a[8]  += v0.x*v2.x + v0.y*v2.y + v0.z*v2.z + v0.w*v2.w;
        a[9]  += v1.x*v1.x + v1.y*v1.y + v1.z*v1.z + v1.w*v1.w;
        a[10] += v1.x*v2.x + v1.y*v2.y + v1.z*v2.z + v1.w*v2.w;
        a[11] += v2.x*v2.x + v2.y*v2.y + v2.z*v2.z + v2.w*v2.w;
    }

#pragma unroll
    for (int i = 0; i < 12; i++) {
        float v = a[i];
#pragma unroll
        for (int off = 16; off; off >>= 1)
            v += __shfl_down_sync(0xffffffffu, v, off);
        if ((tid & 31) == 0) atomicAdd(&racc[i], v);
    }
    __syncthreads();

    if (act) {
        const float ker0 = racc[0] + racc[3];
        const float ker1 = racc[1] + racc[4];
        const float ker2 = racc[2] + racc[5];
        const float c0 = ker0 * racc[6] + ker1 * racc[7]  + ker2 * racc[8];
        const float c1 = ker0 * racc[7] + ker1 * racc[9]  + ker2 * racc[10];
        const float c2 = ker0 * racc[8] + ker1 * racc[10] + ker2 * racc[11];
        const float4 g0 = *(const float4*)&g[hh];
        const float4 g1 = *(const float4*)&g[768 + hh];
        const float4 g2 = *(const float4*)&g[1536 + hh];
        float4 o;
        o.x = ker0*v4[0].x + ker1*v4[1].x + ker2*v4[2].x + c0*g0.x + c1*g1.x + c2*g2.x;
        o.y = ker0*v4[0].y + ker1*v4[1].y + ker2*v4[2].y + c0*g0.y + c1*g1.y + c2*g2.y;
        o.z = ker0*v4[0].z + ker1*v4[1].z + ker2*v4[2].z + c0*g0.z + c1*g1.z + c2*g2.z;
        o.w = ker0*v4[0].w + ker1*v4[1].w + ker2*v4[2].w + c0*g0.w + c1*g1.w + c2*g2.w;
        *(float4*)&out[(size_t)b * 768 + hh] = o;
    }
}

// ---------------- launch -----------------------------------------------------
extern "C" void kernel_launch(void* const* d_in, const int* in_sizes, int n_in,
                              void* d_out, int out_size) {
    const float* target = (const float*)d_in[0];
    const float* cont   = (const float*)d_in[1];
    const float* Wq     = (const float*)d_in[2];
    const float* bq     = (const float*)d_in[3];
    const float* Wk     = (const float*)d_in[4];
    const float* bk     = (const float*)d_in[5];
    const float* Wv     = (const float*)d_in[6];
    const float* bv     = (const float*)d_in[7];
    const float* p      = (const float*)d_in[8];
    const float* hmat   = (const float*)d_in[9];
    const float* g      = (const float*)d_in[10];
    float* out = (float*)d_out;

    split_bf16_kernel<<<3264, 256>>>(target, cont, Wq, Wk, Wv);
    qkv_gemm_bf16<<<336, 256>>>(bq, bk, bv);
    batch_epilogue<<<512, 256>>>(p, hmat, g, out);
}

// round 5
// speedup vs baseline: 4.3663x; 1.2717x over previous
#include <cuda_runtime.h>
#include <cuda_bf16.h>
#include <cstdint>
#include <cstddef>

// ---------------- scratch (allocation-free rule: __device__ globals) --------
__device__ float g_Q[512 * 768];
__device__ float g_K[1536 * 768];
__device__ float g_V[1536 * 768];

// bf16 hi/lo planes. A = [target(512) ; cont(1536)] rows of 768.
__device__ __align__(16) __nv_bfloat16 g_Ah[2048 * 768];
__device__ __align__(16) __nv_bfloat16 g_Al[2048 * 768];
__device__ __align__(16) __nv_bfloat16 g_Wh[3 * 768 * 768];   // Wq|Wk|Wv
__device__ __align__(16) __nv_bfloat16 g_Wl[3 * 768 * 768];

// ---------------- helpers ---------------------------------------------------
__device__ __forceinline__ uint32_t smem_u32(const void* p) {
    uint32_t a;
    asm("{ .reg .u64 t; cvta.to.shared.u64 t, %1; cvt.u32.u64 %0, t; }" : "=r"(a) : "l"(p));
    return a;
}
__device__ __forceinline__ void cp16(uint32_t dst, const void* src) {
    asm volatile("cp.async.cg.shared.global [%0], [%1], 16;" :: "r"(dst), "l"(src) : "memory");
}
__device__ __forceinline__ void cp_commit() {
    asm volatile("cp.async.commit_group;" ::: "memory");
}
__device__ __forceinline__ void ldmx4(uint32_t* r, uint32_t addr) {
    asm volatile("ldmatrix.sync.aligned.m8n8.x4.shared.b16 {%0,%1,%2,%3}, [%4];"
                 : "=r"(r[0]), "=r"(r[1]), "=r"(r[2]), "=r"(r[3]) : "r"(addr));
}
__device__ __forceinline__ void mma_bf16(float* c, const uint32_t* a,
                                         uint32_t b0, uint32_t b1) {
    asm volatile(
        "mma.sync.aligned.m16n8k16.row.col.f32.bf16.bf16.f32 "
        "{%0,%1,%2,%3}, {%4,%5,%6,%7}, {%8,%9}, {%0,%1,%2,%3};"
        : "+f"(c[0]), "+f"(c[1]), "+f"(c[2]), "+f"(c[3])
        : "r"(a[0]), "r"(a[1]), "r"(a[2]), "r"(a[3]), "r"(b0), "r"(b1));
}

// ---------------- pre-pass: fp32 -> bf16 hi/lo split ------------------------
// float4 index space: [0,98304) target, [98304,393216) cont,
// [393216,835584) W planes (147456 float4 each: Wq, Wk, Wv).
__global__ __launch_bounds__(256)
void split_bf16_kernel(const float* __restrict__ t, const float* __restrict__ c,
                       const float* __restrict__ wq, const float* __restrict__ wk,
                       const float* __restrict__ wv) {
    const int base = blockIdx.x * 512 + threadIdx.x;
#pragma unroll
    for (int rep = 0; rep < 2; rep++) {
        const int idx = base + rep * 256;
        if (idx >= 835584) return;
        float4 x;
        __nv_bfloat16 *dh, *dl;
        size_t slot;
        if (idx < 393216) {
            x = (idx < 98304) ? ((const float4*)t)[idx] : ((const float4*)c)[idx - 98304];
            dh = g_Ah; dl = g_Al; slot = idx;
        } else {
            int w = idx - 393216;
            int plane = w / 147456, wi = w % 147456;
            const float4* s = (const float4*)(plane == 0 ? wq : (plane == 1 ? wk : wv));
            x = s[wi];
            dh = g_Wh; dl = g_Wl; slot = w;
        }
        const float xs[4] = {x.x, x.y, x.z, x.w};
        unsigned short hs[4], ls[4];
#pragma unroll
        for (int j = 0; j < 4; j++) {
            __nv_bfloat16 h = __float2bfloat16_rn(xs[j]);
            float r = xs[j] - __bfloat162float(h);
            __nv_bfloat16 l = __float2bfloat16_rn(r);
            hs[j] = __bfloat16_as_ushort(h);
            ls[j] = __bfloat16_as_ushort(l);
        }
        uint2 ph, pl;
        ph.x = (uint32_t)hs[0] | ((uint32_t)hs[1] << 16);
        ph.y = (uint32_t)hs[2] | ((uint32_t)hs[3] << 16);
        pl.x = (uint32_t)ls[0] | ((uint32_t)ls[1] << 16);
        pl.y = (uint32_t)ls[2] | ((uint32_t)ls[3] << 16);
        ((uint2*)dh)[slot] = ph;
        ((uint2*)dl)[slot] = pl;
    }
}

// ---------------- fused QKV GEMM: bf16x3 mma.sync m16n8k16 ------------------
// C = A @ W^T + bias. 112 CTAs (single wave) of BM=128 x BN=192 tiles:
//   [0,16)=Q, [16,64)=K, [64,112)=V.  K chunked by 16 (48 chunks), cp.async
//   double buffer. Swizzled 32B smem rows (conflict-free ldmatrix).
// 8 warps as 2(m) x 4(n): warp tile 64x48. Per warp per chunk: 72 mma.
#define NCH   48
#define STAGE 20480      // Ah 4096 | Al 4096 | Bh 6144 | Bl 6144

__global__ __launch_bounds__(256)
void qkv_gemm_bf16(const float* __restrict__ bq, const float* __restrict__ bk,
                   const float* __restrict__ bv) {
    __shared__ __align__(16) char smem[2 * STAGE];
    const uint32_t sb = smem_u32(smem);

    const int tid = threadIdx.x, lane = tid & 31, wid = tid >> 5;
    const int blk = blockIdx.x;

    int by, bx, rowA0, plane;
    const float* bias;
    float* C;
    if (blk < 16)      { int t = blk;      by = t >> 2; bx = t & 3; rowA0 = by * 128;       plane = 0; bias = bq; C = g_Q; }
    else if (blk < 64) { int t = blk - 16; by = t >> 2; bx = t & 3; rowA0 = 512 + by * 128; plane = 1; bias = bk; C = g_K; }
    else               { int t = blk - 64; by = t >> 2; bx = t & 3; rowA0 = 512 + by * 128; plane = 2; bias = bv; C = g_V; }

    const char* srcAh = (const char*)g_Ah + (size_t)rowA0 * 1536;
    const char* srcAl = (const char*)g_Al + (size_t)rowA0 * 1536;
    const char* srcBh = (const char*)g_Wh + (size_t)plane * 1179648 + (size_t)(bx * 192) * 1536;
    const char* srcBl = (const char*)g_Wl + (size_t)plane * 1179648 + (size_t)(bx * 192) * 1536;

    // --- load decode: 1280 cp16 per stage, 5 per thread ----------------------
    uint32_t ldst[5];
    const char* lsrc[5];
#pragma unroll
    for (int i = 0; i < 5; i++) {
        const int id = i * 256 + tid;
        if (id < 512) {                       // A planes: 2 x 128 rows x 2 subs
            const int pl = id >> 8, rem = id & 255, row = rem >> 1, sub = rem & 1;
            const int u = (sub ^ (row >> 2)) & 1;
            ldst[i] = pl * 4096 + row * 32 + u * 16;
            lsrc[i] = (pl ? srcAl : srcAh) + (size_t)row * 1536 + sub * 16;
        } else {                              // B planes: 2 x 192 rows x 2 subs
            const int id2 = id - 512;
            const int pl = (id2 >= 384) ? 1 : 0;
            const int rem = id2 - pl * 384, row = rem >> 1, sub = rem & 1;
            const int u = (sub ^ (row >> 2)) & 1;
            ldst[i] = 8192 + pl * 6144 + row * 32 + u * 16;
            lsrc[i] = (pl ? srcBl : srcBh) + (size_t)row * 1536 + sub * 16;
        }
    }

    const int warp_m = (wid >> 2) * 64;   // 0 or 64
    const int warp_n = (wid & 3) * 48;    // 0,48,96,144

    // ldmatrix lane addressing
    const int a_row = lane & 15;
    const int a_sub = (lane >> 4) & 1;
    const int b_row = ((lane >> 4) & 1) * 8 + (lane & 7);
    const int b_sub = (lane >> 3) & 1;

    float acc[4][6][4];
#pragma unroll
    for (int mf = 0; mf < 4; mf++)
#pragma unroll
        for (int j = 0; j < 6; j++)
#pragma unroll
            for (int i = 0; i < 4; i++) acc[mf][j][i] = 0.f;

    // prologue: stage 0
#pragma unroll
    for (int i = 0; i < 5; i++) cp16(sb + ldst[i], lsrc[i]);
    cp_commit();

    for (int c = 0; c < NCH; c++) {
        const int buf = c & 1;
        if (c + 1 < NCH) {
            const uint32_t nb = sb + (buf ^ 1) * STAGE;
            const size_t off = (size_t)(c + 1) * 32;
#pragma unroll
            for (int i = 0; i < 5; i++) cp16(nb + ldst[i], lsrc[i] + off);
            cp_commit();
            asm volatile("cp.async.wait_group 1;" ::: "memory");
        } else {
            asm volatile("cp.async.wait_group 0;" ::: "memory");
        }
        __syncthreads();

        const uint32_t st = sb + buf * STAGE;
        uint32_t ah[4][4], al[4][4], bh[3][4], bl[3][4];
#pragma unroll
        for (int mf = 0; mf < 4; mf++) {
            const int row = warp_m + mf * 16 + a_row;
            const uint32_t ra = st + row * 32 + ((a_sub ^ (row >> 2)) & 1) * 16;
            ldmx4(ah[mf], ra);
            ldmx4(al[mf], ra + 4096);
        }
#pragma unroll
        for (int ng = 0; ng < 3; ng++) {
            const int row = warp_n + ng * 16 + b_row;
            const uint32_t rb = st + 8192 + row * 32 + ((b_sub ^ (row >> 2)) & 1) * 16;
            ldmx4(bh[ng], rb);
            ldmx4(bl[ng], rb + 6144);
        }
        // term-major issue order: same-acc RAW deps are 24 mma apart
#pragma unroll
        for (int mf = 0; mf < 4; mf++)
#pragma unroll
            for (int j = 0; j < 6; j++)
                mma_bf16(acc[mf][j], ah[mf], bh[j >> 1][(j & 1) * 2], bh[j >> 1][(j & 1) * 2 + 1]);
#pragma unroll
        for (int mf = 0; mf < 4; mf++)
#pragma unroll
            for (int j = 0; j < 6; j++)
                mma_bf16(acc[mf][j], ah[mf], bl[j >> 1][(j & 1) * 2], bl[j >> 1][(j & 1) * 2 + 1]);
#pragma unroll
        for (int mf = 0; mf < 4; mf++)
#pragma unroll
            for (int j = 0; j < 6; j++)
                mma_bf16(acc[mf][j], al[mf], bh[j >> 1][(j & 1) * 2], bh[j >> 1][(j & 1) * 2 + 1]);
        __syncthreads();
    }

    // epilogue: bias + store fp32
    const int g4 = lane >> 2, t4 = lane & 3;
#pragma unroll
    for (int mf = 0; mf < 4; mf++) {
        const int row = by * 128 + warp_m + mf * 16 + g4;
#pragma unroll
        for (int j = 0; j < 6; j++) {
            const int col = bx * 192 + warp_n + j * 8 + t4 * 2;
            const float2 bb = *(const float2*)&bias[col];
            float2 o0, o1;
            o0.x = acc[mf][j][0] + bb.x; o0.y = acc[mf][j][1] + bb.y;
            o1.x = acc[mf][j][2] + bb.x; o1.y = acc[mf][j][3] + bb.y;
            *(float2*)&C[(size_t)row * 768 + col]       = o0;
            *(float2*)&C[(size_t)(row + 8) * 768 + col] = o1;
        }
    }
}

// ---------------- per-batch epilogue (vectorized) ---------------------------
__global__ __launch_bounds__(256)
void batch_epilogue(const float* __restrict__ p, const float* __restrict__ hmat,
                    const float* __restrict__ g, float* __restrict__ out) {
    const int b = blockIdx.x, tid = threadIdx.x;
    __shared__ float racc[12];
    if (tid < 12) racc[tid] = 0.f;
    __syncthreads();

    const bool act = tid < 192;
    const int hh = tid * 4;
    float a[12];
#pragma unroll
    for (int i = 0; i < 12; i++) a[i] = 0.f;

    float4 v4[3];
    if (act) {
        const float4 q4 = *(const float4*)&g_Q[(size_t)b * 768 + hh];
#pragma unroll
        for (int mp = 0; mp < 3; mp++) {
            const float4 k4 = *(const float4*)&g_K[((size_t)b * 3 + mp) * 768 + hh];
            v4[mp]          = *(const float4*)&g_V[((size_t)b * 3 + mp) * 768 + hh];
            const float4 pm = *(const float4*)&p[mp * 768 + hh];
            a[mp] += pm.x * q4.x + pm.y * q4.y + pm.z * q4.z + pm.w * q4.w;

            const float4* hrp = (const float4*)&hmat[((size_t)(mp * 768 + hh)) * 3];
            const float4 f0 = hrp[0], f1 = hrp[1], f2 = hrp[2];
            const float hr[12] = {f0.x, f0.y, f0.z, f0.w, f1.x, f1.y,
                                  f1.z, f1.w, f2.x, f2.y, f2.z, f2.w};
            const float t[4] = {q4.x * k4.x, q4.y * k4.y, q4.z * k4.z, q4.w * k4.w};
#pragma unroll
            for (int e = 0; e < 4; e++) {
                a[3] += t[e] * hr[e * 3 + 0];
                a[4] += t[e] * hr[e * 3 + 1];
                a[5] += t[e] * hr[e * 3 + 2];
            }
        }
        const float4 v0 = v4[0], v1 = v4[1], v2 = v4[2];
        a[6]  += v0.x*v0.x + v0.y*v0.y + v0.z*v0.z + v0.w*v0.w;
        a[7]  += v0.x*v1.x + v0.y*v1.y + v0.z*v1.z + v0.w*v1.w;
        a[8]  += v0.x*v2.x + v0.y*v2.y + v0.z*v2.z + v0.w*v2.w;
        a[9]  += v1.x*v1.x + v1.y*v1.y + v1.z*v1.z + v1.w*v1.w;
        a[10] += v1.x*v2.x + v1.y*v2.y + v1.z*v2.z + v1.w*v2.w;
        a[11] += v2.x*v2.x + v2.y*v2.y + v2.z*v2.z + v2.w*v2.w;
    }

#pragma unroll
    for (int i = 0; i < 12; i++) {
        float v = a[i];
#pragma unroll
        for (int off = 16; off; off >>= 1)
            v += __shfl_down_sync(0xffffffffu, v, off);
        if ((tid & 31) == 0) atomicAdd(&racc[i], v);
    }
    __syncthreads();

    if (act) {
        const float ker0 = racc[0] + racc[3];
        const float ker1 = racc[1] + racc[4];
        const float ker2 = racc[2] + racc[5];
        const float c0 = ker0 * racc[6] + ker1 * racc[7]  + ker2 * racc[8];
        const float c1 = ker0 * racc[7] + ker1 * racc[9]  + ker2 * racc[10];
        const float c2 = ker0 * racc[8] + ker1 * racc[10] + ker2 * racc[11];
        const float4 g0 = *(const float4*)&g[hh];
        const float4 g1 = *(const float4*)&g[768 + hh];
        const float4 g2 = *(const float4*)&g[1536 + hh];
        float4 o;
        o.x = ker0*v4[0].x + ker1*v4[1].x + ker2*v4[2].x + c0*g0.x + c1*g1.x + c2*g2.x;
        o.y = ker0*v4[0].y + ker1*v4[1].y + ker2*v4[2].y + c0*g0.y + c1*g1.y + c2*g2.y;
        o.z = ker0*v4[0].z + ker1*v4[1].z + ker2*v4[2].z + c0*g0.z + c1*g1.z + c2*g2.z;
        o.w = ker0*v4[0].w + ker1*v4[1].w + ker2*v4[2].w + c0*g0.w + c1*g1.w + c2*g2.w;
        *(float4*)&out[(size_t)b * 768 + hh] = o;
    }
}

// ---------------- launch -----------------------------------------------------
extern "C" void kernel_launch(void* const* d_in, const int* in_sizes, int n_in,
                              void* d_out, int out_size) {
    const float* target = (const float*)d_in[0];
    const float* cont   = (const float*)d_in[1];
    const float* Wq     = (const float*)d_in[2];
    const float* bq     = (const float*)d_in[3];
    const float* Wk     = (const float*)d_in[4];
    const float* bk     = (const float*)d_in[5];
    const float* Wv     = (const float*)d_in[6];
    const float* bv     = (const float*)d_in[7];
    const float* p      = (const float*)d_in[8];
    const float* hmat   = (const float*)d_in[9];
    const float* g      = (const float*)d_in[10];
    float* out = (float*)d_out;

    split_bf16_kernel<<<1632, 256>>>(target, cont, Wq, Wk, Wv);
    qkv_gemm_bf16<<<112, 256>>>(bq, bk, bv);
    batch_epilogue<<<512, 256>>>(p, hmat, g, out);
}

// round 6
// speedup vs baseline: 5.3883x; 1.2341x over previous
#include <cuda_runtime.h>
#include <cuda_bf16.h>
#include <cstdint>
#include <cstddef>

// ---------------- scratch (allocation-free rule: __device__ globals) --------
__device__ float g_Q[512 * 768];
__device__ float g_K[1536 * 768];
__device__ float g_V[1536 * 768];

// ---------------- helpers ---------------------------------------------------
__device__ __forceinline__ void ldmx4(uint32_t* r, uint32_t addr) {
    asm volatile("ldmatrix.sync.aligned.m8n8.x4.shared.b16 {%0,%1,%2,%3}, [%4];"
                 : "=r"(r[0]), "=r"(r[1]), "=r"(r[2]), "=r"(r[3]) : "r"(addr));
}
__device__ __forceinline__ uint32_t smem_u32(const void* p) {
    uint32_t a;
    asm("{ .reg .u64 t; cvta.to.shared.u64 t, %1; cvt.u32.u64 %0, t; }" : "=r"(a) : "l"(p));
    return a;
}
__device__ __forceinline__ void mma_bf16(float* c, const uint32_t* a,
                                         uint32_t b0, uint32_t b1) {
    asm volatile(
        "mma.sync.aligned.m16n8k16.row.col.f32.bf16.bf16.f32 "
        "{%0,%1,%2,%3}, {%4,%5,%6,%7}, {%8,%9}, {%0,%1,%2,%3};"
        : "+f"(c[0]), "+f"(c[1]), "+f"(c[2]), "+f"(c[3])
        : "r"(a[0]), "r"(a[1]), "r"(a[2]), "r"(a[3]), "r"(b0), "r"(b1));
}
// split one float into (hi, lo) bf16 pair, packed as two bf16 in each u32 later
__device__ __forceinline__ void split1(float x, unsigned short& h, unsigned short& l) {
    __nv_bfloat16 hb = __float2bfloat16_rn(x);
    float r = x - __bfloat162float(hb);
    __nv_bfloat16 lb = __float2bfloat16_rn(r);
    h = __bfloat16_as_ushort(hb);
    l = __bfloat16_as_ushort(lb);
}

// ---------------- fused QKV GEMM: bf16x3 mma.sync m16n8k16 ------------------
// C = A @ W^T + bias with in-kernel fp32 -> bf16 hi/lo split (no prepass).
// 112 CTAs (single wave), BM=128 x BN=192, K chunked by 16 (48 chunks).
//   [0,16)=Q, [16,64)=K, [64,112)=V.
// smem stage (20KB): Ah[4K] Al[4K] Bh[6K] Bl[6K], 32B swizzled rows; x2 buffers.
// 8 warps as 2(m) x 4(n): warp tile 64x48 -> 72 mma per warp per chunk.
#define NCH   48
#define STAGE 20480

__global__ __launch_bounds__(256)
void qkv_gemm_bf16(const float* __restrict__ target, const float* __restrict__ cont,
                   const float* __restrict__ wq, const float* __restrict__ wk,
                   const float* __restrict__ wv,
                   const float* __restrict__ bq, const float* __restrict__ bk,
                   const float* __restrict__ bv) {
    __shared__ __align__(16) char smem[2 * STAGE];

    const int tid = threadIdx.x, lane = tid & 31, wid = tid >> 5;
    const int blk = blockIdx.x;

    int by, bx, plane;
    const float *srcA, *bias;
    float* C;
    if (blk < 16)      { int t = blk;      by = t >> 2; bx = t & 3; srcA = target + (size_t)(by * 128) * 768; plane = 0; bias = bq; C = g_Q; }
    else if (blk < 64) { int t = blk - 16; by = t >> 2; bx = t & 3; srcA = cont   + (size_t)(by * 128) * 768; plane = 1; bias = bk; C = g_K; }
    else               { int t = blk - 64; by = t >> 2; bx = t & 3; srcA = cont   + (size_t)(by * 128) * 768; plane = 2; bias = bv; C = g_V; }
    const float* srcB = (plane == 0 ? wq : (plane == 1 ? wk : wv)) + (size_t)(bx * 192) * 768;

    // --- load decode: 1280 16B-float4 slots per chunk, 5 per thread ----------
    // id < 512:  A rows (128 x 4 segs); id >= 512: B rows (192 x 4 segs).
    const float* gsrc[5];
    int sdst_hi[5], lo_off[5];
#pragma unroll
    for (int i = 0; i < 5; i++) {
        const int id = i * 256 + tid;
        int row, seg, base;
        if (id < 512) { row = id >> 2;          seg = id & 3; base = 0;    lo_off[i] = 4096;
                        gsrc[i] = srcA + (size_t)row * 768 + seg * 4; }
        else          { const int id2 = id - 512; row = id2 >> 2; seg = id2 & 3; base = 8192; lo_off[i] = 6144;
                        gsrc[i] = srcB + (size_t)row * 768 + seg * 4; }
        const int half = ((seg >> 1) ^ (row >> 2)) & 1;
        sdst_hi[i] = base + row * 32 + half * 16 + (seg & 1) * 8;
    }

    const int warp_m = (wid >> 2) * 64;
    const int warp_n = (wid & 3) * 48;

    const int a_row = lane & 15;
    const int a_sub = (lane >> 4) & 1;
    const int b_row = ((lane >> 4) & 1) * 8 + (lane & 7);
    const int b_sub = (lane >> 3) & 1;

    const uint32_t sb = smem_u32(smem);

    float acc[4][6][4];
#pragma unroll
    for (int mf = 0; mf < 4; mf++)
#pragma unroll
        for (int j = 0; j < 6; j++)
#pragma unroll
            for (int i = 0; i < 4; i++) acc[mf][j][i] = 0.f;

    float4 r[5];
    // prologue: chunk 0 -> buf 0
#pragma unroll
    for (int i = 0; i < 5; i++) r[i] = *(const float4*)(gsrc[i]);
    {
        char* st = smem;
#pragma unroll
        for (int i = 0; i < 5; i++) {
            unsigned short h0,l0,h1,l1,h2,l2,h3,l3;
            split1(r[i].x, h0, l0); split1(r[i].y, h1, l1);
            split1(r[i].z, h2, l2); split1(r[i].w, h3, l3);
            uint2 ph, pl;
            ph.x = (uint32_t)h0 | ((uint32_t)h1 << 16);
            ph.y = (uint32_t)h2 | ((uint32_t)h3 << 16);
            pl.x = (uint32_t)l0 | ((uint32_t)l1 << 16);
            pl.y = (uint32_t)l2 | ((uint32_t)l3 << 16);
            *(uint2*)(st + sdst_hi[i])             = ph;
            *(uint2*)(st + sdst_hi[i] + lo_off[i]) = pl;
        }
    }
    __syncthreads();
    // preload chunk 1 into registers
#pragma unroll
    for (int i = 0; i < 5; i++) r[i] = *(const float4*)(gsrc[i] + 16);

    for (int c = 0; c < NCH; c++) {
        const int buf = c & 1;
        const uint32_t st = sb + buf * STAGE;

        // fragments for this chunk
        uint32_t ah[4][4], al[4][4], bh[3][4], bl[3][4];
#pragma unroll
        for (int mf = 0; mf < 4; mf++) {
            const int row = warp_m + mf * 16 + a_row;
            const uint32_t ra = st + row * 32 + ((a_sub ^ (row >> 2)) & 1) * 16;
            ldmx4(ah[mf], ra);
            ldmx4(al[mf], ra + 4096);
        }
#pragma unroll
        for (int ng = 0; ng < 3; ng++) {
            const int row = warp_n + ng * 16 + b_row;
            const uint32_t rb = st + 8192 + row * 32 + ((b_sub ^ (row >> 2)) & 1) * 16;
            ldmx4(bh[ng], rb);
            ldmx4(bl[ng], rb + 6144);
        }

        // store chunk c+1 (held in r) into the other buffer
        if (c + 1 < NCH) {
            char* stn = smem + (buf ^ 1) * STAGE;
#pragma unroll
            for (int i = 0; i < 5; i++) {
                unsigned short h0,l0,h1,l1,h2,l2,h3,l3;
                split1(r[i].x, h0, l0); split1(r[i].y, h1, l1);
                split1(r[i].z, h2, l2); split1(r[i].w, h3, l3);
                uint2 ph, pl;
                ph.x = (uint32_t)h0 | ((uint32_t)h1 << 16);
                ph.y = (uint32_t)h2 | ((uint32_t)h3 << 16);
                pl.x = (uint32_t)l0 | ((uint32_t)l1 << 16);
                pl.y = (uint32_t)l2 | ((uint32_t)l3 << 16);
                *(uint2*)(stn + sdst_hi[i])             = ph;
                *(uint2*)(stn + sdst_hi[i] + lo_off[i]) = pl;
            }
            // issue LDG for chunk c+2 (clamped); latency hidden under mma below
            const int nc = (c + 2 < NCH) ? (c + 2) : (NCH - 1);
            const size_t off = (size_t)nc * 16;
#pragma unroll
            for (int i = 0; i < 5; i++) r[i] = *(const float4*)(gsrc[i] + off);
        }

        // term-major mma: same-acc RAW deps 24 instructions apart
#pragma unroll
        for (int mf = 0; mf < 4; mf++)
#pragma unroll
            for (int j = 0; j < 6; j++)
                mma_bf16(acc[mf][j], ah[mf], bh[j >> 1][(j & 1) * 2], bh[j >> 1][(j & 1) * 2 + 1]);
#pragma unroll
        for (int mf = 0; mf < 4; mf++)
#pragma unroll
            for (int j = 0; j < 6; j++)
                mma_bf16(acc[mf][j], ah[mf], bl[j >> 1][(j & 1) * 2], bl[j >> 1][(j & 1) * 2 + 1]);
#pragma unroll
        for (int mf = 0; mf < 4; mf++)
#pragma unroll
            for (int j = 0; j < 6; j++)
                mma_bf16(acc[mf][j], al[mf], bh[j >> 1][(j & 1) * 2], bh[j >> 1][(j & 1) * 2 + 1]);

        __syncthreads();
    }

    // epilogue: bias + store fp32
    const int g4 = lane >> 2, t4 = lane & 3;
#pragma unroll
    for (int mf = 0; mf < 4; mf++) {
        const int row = by * 128 + warp_m + mf * 16 + g4;
#pragma unroll
        for (int j = 0; j < 6; j++) {
            const int col = bx * 192 + warp_n + j * 8 + t4 * 2;
            const float2 bb = *(const float2*)&bias[col];
            float2 o0, o1;
            o0.x = acc[mf][j][0] + bb.x; o0.y = acc[mf][j][1] + bb.y;
            o1.x = acc[mf][j][2] + bb.x; o1.y = acc[mf][j][3] + bb.y;
            *(float2*)&C[(size_t)row * 768 + col]       = o0;
            *(float2*)&C[(size_t)(row + 8) * 768 + col] = o1;
        }
    }
}

// ---------------- per-batch epilogue (192 threads, all active) --------------
__global__ __launch_bounds__(192)
void batch_epilogue(const float* __restrict__ p, const float* __restrict__ hmat,
                    const float* __restrict__ g, float* __restrict__ out) {
    const int b = blockIdx.x, tid = threadIdx.x;
    __shared__ float racc[12];
    if (tid < 12) racc[tid] = 0.f;
    __syncthreads();

    const int hh = tid * 4;
    float a[12];
#pragma unroll
    for (int i = 0; i < 12; i++) a[i] = 0.f;

    float4 v4[3];
    const float4 q4 = *(const float4*)&g_Q[(size_t)b * 768 + hh];
#pragma unroll
    for (int mp = 0; mp < 3; mp++) {
        const float4 k4 = *(const float4*)&g_K[((size_t)b * 3 + mp) * 768 + hh];
        v4[mp]          = *(const float4*)&g_V[((size_t)b * 3 + mp) * 768 + hh];
        const float4 pm = *(const float4*)&p[mp * 768 + hh];
        a[mp] += pm.x * q4.x + pm.y * q4.y + pm.z * q4.z + pm.w * q4.w;

        const float4* hrp = (const float4*)&hmat[((size_t)(mp * 768 + hh)) * 3];
        const float4 f0 = hrp[0], f1 = hrp[1], f2 = hrp[2];
        const float hr[12] = {f0.x, f0.y, f0.z, f0.w, f1.x, f1.y,
                              f1.z, f1.w, f2.x, f2.y, f2.z, f2.w};
        const float t[4] = {q4.x * k4.x, q4.y * k4.y, q4.z * k4.z, q4.w * k4.w};
#pragma unroll
        for (int e = 0; e < 4; e++) {
            a[3] += t[e] * hr[e * 3 + 0];
            a[4] += t[e] * hr[e * 3 + 1];
            a[5] += t[e] * hr[e * 3 + 2];
        }
    }
    const float4 v0 = v4[0], v1 = v4[1], v2 = v4[2];
    a[6]  += v0.x*v0.x + v0.y*v0.y + v0.z*v0.z + v0.w*v0.w;
    a[7]  += v0.x*v1.x + v0.y*v1.y + v0.z*v1.z + v0.w*v1.w;
    a[8]  += v0.x*v2.x + v0.y*v2.y + v0.z*v2.z + v0.w*v2.w;
    a[9]  += v1.x*v1.x + v1.y*v1.y + v1.z*v1.z + v1.w*v1.w;
    a[10] += v1.x*v2.x + v1.y*v2.y + v1.z*v2.z + v1.w*v2.w;
    a[11] += v2.x*v2.x + v2.y*v2.y + v2.z*v2.z + v2.w*v2.w;

#pragma unroll
    for (int i = 0; i < 12; i++) {
        float v = a[i];
#pragma unroll
        for (int off = 16; off; off >>= 1)
            v += __shfl_down_sync(0xffffffffu, v, off);
        if ((tid & 31) == 0) atomicAdd(&racc[i], v);
    }
    __syncthreads();

    const float ker0 = racc[0] + racc[3];
    const float ker1 = racc[1] + racc[4];
    const float ker2 = racc[2] + racc[5];
    const float c0 = ker0 * racc[6] + ker1 * racc[7]  + ker2 * racc[8];
    const float c1 = ker0 * racc[7] + ker1 * racc[9]  + ker2 * racc[10];
    const float c2 = ker0 * racc[8] + ker1 * racc[10] + ker2 * racc[11];
    const float4 g0 = *(const float4*)&g[hh];
    const float4 g1 = *(const float4*)&g[768 + hh];
    const float4 g2 = *(const float4*)&g[1536 + hh];
    float4 o;
    o.x = ker0*v4[0].x + ker1*v4[1].x + ker2*v4[2].x + c0*g0.x + c1*g1.x + c2*g2.x;
    o.y = ker0*v4[0].y + ker1*v4[1].y + ker2*v4[2].y + c0*g0.y + c1*g1.y + c2*g2.y;
    o.z = ker0*v4[0].z + ker1*v4[1].z + ker2*v4[2].z + c0*g0.z + c1*g1.z + c2*g2.z;
    o.w = ker0*v4[0].w + ker1*v4[1].w + ker2*v4[2].w + c0*g0.w + c1*g1.w + c2*g2.w;
    *(float4*)&out[(size_t)b * 768 + hh] = o;
}

// ---------------- launch -----------------------------------------------------
extern "C" void kernel_launch(void* const* d_in, const int* in_sizes, int n_in,
                              void* d_out, int out_size) {
    const float* target = (const float*)d_in[0];
    const float* cont   = (const float*)d_in[1];
    const float* Wq     = (const float*)d_in[2];
    const float* bq     = (const float*)d_in[3];
    const float* Wk     = (const float*)d_in[4];
    const float* bk     = (const float*)d_in[5];
    const float* Wv     = (const float*)d_in[6];
    const float* bv     = (const float*)d_in[7];
    const float* p      = (const float*)d_in[8];
    const float* hmat   = (const float*)d_in[9];
    const float* g      = (const float*)d_in[10];
    float* out = (float*)d_out;

    qkv_gemm_bf16<<<112, 256>>>(target, cont, Wq, Wk, Wv, bq, bk, bv);
    batch_epilogue<<<512, 192>>>(p, hmat, g, out);
}